// round 16
// baseline (speedup 1.0000x reference)
#include <cuda_runtime.h>
#include <cuda_bf16.h>
#include <cstdint>
#include <cstddef>

#define N_NODES 8192
#define DHID 64

// ---------------- scratch (device globals; no allocation allowed) ----------------
__device__ __align__(16) __nv_bfloat16 g_HclT[DHID * N_NODES];  // H_cl^T bf16 [64][8192]
__device__ __align__(16) __nv_bfloat16 g_HueT[DHID * N_NODES];  // H_ue^T bf16 [64][8192]
__device__ __align__(16) __nv_bfloat16 g_AclB[(size_t)N_NODES * N_NODES];  // bf16 copy of A_cl
__device__ __align__(16) __nv_bfloat16 g_AueB[(size_t)N_NODES * N_NODES];  // bf16 copy of A_ue
__device__ __align__(16) float g_Xc1[N_NODES * DHID];
__device__ __align__(16) float g_Xc2[N_NODES * DHID];
__device__ __align__(16) float g_Xue[N_NODES * DHID];
__device__ __align__(16) float g_part[512 * DHID];

__device__ __forceinline__ float relu_(float x) { return fmaxf(x, 0.0f); }

__device__ __forceinline__ uint32_t smem_u32(const void* p) {
    uint32_t a;
    asm("{ .reg .u64 t; cvta.to.shared.u64 t, %1; cvt.u32.u64 %0, t; }" : "=r"(a) : "l"(p));
    return a;
}

__device__ __forceinline__ void ldsm_x4(uint32_t* r, uint32_t addr) {
    asm volatile("ldmatrix.sync.aligned.m8n8.x4.shared.b16 {%0,%1,%2,%3}, [%4];"
                 : "=r"(r[0]), "=r"(r[1]), "=r"(r[2]), "=r"(r[3]) : "r"(addr));
}

__device__ __forceinline__ void mma_bf16(float* c, const uint32_t* a, uint32_t b0, uint32_t b1) {
    asm volatile(
        "mma.sync.aligned.m16n8k16.row.col.f32.bf16.bf16.f32 "
        "{%0,%1,%2,%3}, {%4,%5,%6,%7}, {%8,%9}, {%0,%1,%2,%3};"
        : "+f"(c[0]), "+f"(c[1]), "+f"(c[2]), "+f"(c[3])
        : "r"(a[0]), "r"(a[1]), "r"(a[2]), "r"(a[3]), "r"(b0), "r"(b1));
}

__device__ __forceinline__ uint32_t pack_bf16x2(float2 v) {
    __nv_bfloat162 b = __float22bfloat162_rn(v);
    return *(uint32_t*)&b;
}

#define CP_ASYNC16(smem, gptr) \
    asm volatile("cp.async.cg.shared.global [%0], [%1], 16;" :: "r"(smem), "l"(gptr))
#define CP_COMMIT() asm volatile("cp.async.commit_group;")

template <int N>
__device__ __forceinline__ void cp_wait() {
    if constexpr (N == 2)      asm volatile("cp.async.wait_group 2;");
    else if constexpr (N == 3) asm volatile("cp.async.wait_group 3;");
    else if constexpr (N == 4) asm volatile("cp.async.wait_group 4;");
    else                       asm volatile("cp.async.wait_group 1;");
}

// ---------------- GEMM body: C[MROWS-row tile, ND] = A @ Ht^T (Ht bf16 [n][k]) ----------------
// ABF=false: A fp32 (LDS+cvt fragments); WB=true writes row-major bf16 A copy to Awb.
// ABF=true:  A bf16 (ldmatrix fragments, 80B-stride layout identical to B).
// NT=1 (MROWS=64): ND=64,  C0 = g_Xc1 (Bt0 = HclT)
// NT=2 (MROWS=32): ND=128, cols 0-63 -> C0 = g_Xc2 (Bt0 = HueT), cols 64-127 -> C1 = g_Xue (Bt1 = HclT)
template <int NT, int MROWS, bool ABF, bool WB, int STAGES>
__device__ __forceinline__ void gemm_body(const void* __restrict__ Av,
                                          const __nv_bfloat16* __restrict__ Bt0,
                                          const __nv_bfloat16* __restrict__ Bt1,
                                          float* __restrict__ C0, float* __restrict__ C1,
                                          __nv_bfloat16* __restrict__ Awb,
                                          int m0, char* smem) {
    constexpr int ND     = 64 * NT;
    constexpr int KC     = 32;                 // k per chunk
    constexpr int NCH    = N_NODES / KC;       // 256 chunks
    constexpr int AST    = ABF ? 80 : 160;     // A smem row stride
    constexpr int ABUF   = MROWS * AST;        // A bytes per stage
    constexpr int BSTR   = 80;                 // bf16 B row stride
    constexpr int BBUF   = ND * BSTR;          // B bytes per stage
    constexpr int NWID   = ND / 4;             // warp n-width (4 N-warps)
    constexpr int NP     = NT;                 // B ldmatrix-x4 per ks per warp
    constexpr int WROWS  = MROWS / 2;          // rows per M-warp
    constexpr int NMT    = WROWS / 16;         // 16-row m-subtiles per warp
    constexpr int ASLOTS = ABF ? MROWS * 4 : MROWS * 8;  // 16B cp.async slots for A
    constexpr int APT    = (ASLOTS + 255) / 256;

    const int tid  = threadIdx.x;
    const int lane = tid & 31;
    const int wid  = tid >> 5;
    const int wm   = wid & 1;                  // 2 M-warps
    const int wn   = wid >> 1;                 // 4 N-warps
    const int g    = lane >> 2;
    const int t    = lane & 3;

    const uint32_t sbu = smem_u32(smem);
    const uint32_t sA0 = sbu;                  // STAGES stages of A
    const uint32_t sB0 = sbu + STAGES * ABUF;  // STAGES stages of B

    // ---- A cp.async slot map ----
    const char* gAp[APT];
    uint32_t aoffS[APT];
    #pragma unroll
    for (int i = 0; i < APT; ++i) {
        int slot = tid + i * 256;
        if (ABF) {
            int row = slot >> 2, seg = slot & 3;       // 16B = 8 bf16
            gAp[i]   = (const char*)((const __nv_bfloat16*)Av + (size_t)(m0 + row) * N_NODES + seg * 8);
            aoffS[i] = (uint32_t)(row * AST + seg * 16);
        } else {
            int row = slot >> 3, seg = slot & 7;       // 16B = 4 floats
            gAp[i]   = (const char*)((const float*)Av + (size_t)(m0 + row) * N_NODES + seg * 4);
            aoffS[i] = (uint32_t)(row * AST + seg * 16);
        }
    }
    // ---- B cp.async slot map: ND rows x 4 x 16B slots, NT per thread ----
    const __nv_bfloat16* gBp[NT];
    uint32_t boffS[NT];
    #pragma unroll
    for (int j = 0; j < NT; ++j) {
        int slot = tid + j * 256;
        int row = slot >> 2, seg = slot & 3;
        const __nv_bfloat16* base = (NT == 2 && row >= 64)
            ? (Bt1 + (size_t)(row - 64) * N_NODES) : (Bt0 + (size_t)row * N_NODES);
        gBp[j]   = base + seg * 8;
        boffS[j] = (uint32_t)(row * BSTR + seg * 16);
    }

    auto ISSUE = [&](int kt, int s) {
        const uint32_t sa = sA0 + s * ABUF;
        const size_t abyte = (size_t)kt * KC * (ABF ? 2 : 4);
        #pragma unroll
        for (int i = 0; i < APT; ++i) {
            if (ASLOTS >= 256 || tid < ASLOTS)
                CP_ASYNC16(sa + aoffS[i], gAp[i] + abyte);
        }
        const uint32_t sb = sB0 + s * BBUF;
        #pragma unroll
        for (int j = 0; j < NT; ++j)
            CP_ASYNC16(sb + boffS[j], gBp[j] + (size_t)kt * KC);
    };

    // ---- B ldmatrix lane offsets (validated layout, 80B stride) ----
    uint32_t boffL[NP][2];
    #pragma unroll
    for (int np = 0; np < NP; ++np)
        #pragma unroll
        for (int ks = 0; ks < 2; ++ks)
            boffL[np][ks] = (uint32_t)((wn * NWID + np * 16 + (lane >> 4) * 8 + (lane & 7)) * BSTR +
                                       (ks * 16 + ((lane >> 3) & 1) * 8) * 2);

    // ---- A fragment offsets ----
    uint32_t aoffL[NMT][2];
    #pragma unroll
    for (int mt = 0; mt < NMT; ++mt)
        #pragma unroll
        for (int ks = 0; ks < 2; ++ks)
            aoffL[mt][ks] = (uint32_t)((wm * WROWS + mt * 16 + (lane & 15)) * AST +
                                       ks * 32 + (lane >> 4) * 16);
    const int afrag_base = (wm * WROWS + g) * AST + t * 8;

    float acc[NMT][2 * NP][4];
    #pragma unroll
    for (int mt = 0; mt < NMT; ++mt)
        #pragma unroll
        for (int nt = 0; nt < 2 * NP; ++nt)
            #pragma unroll
            for (int i = 0; i < 4; ++i) acc[mt][nt][i] = 0.0f;

    // ---- prologue: fill STAGES-1 stages ----
    #pragma unroll
    for (int s = 0; s < STAGES - 1; ++s) { ISSUE(s, s); CP_COMMIT(); }

    int st = 0;               // stage of current chunk
    int sti = STAGES - 1;     // stage to issue into
    for (int kt = 0; kt < NCH; ++kt) {
        cp_wait<STAGES - 2>();
        __syncthreads();

        if (kt + STAGES - 1 < NCH) ISSUE(kt + STAGES - 1, sti);
        CP_COMMIT();

        const char*    As = smem + st * ABUF;
        const uint32_t Au = sA0 + st * ABUF;
        const uint32_t Bb = sB0 + st * BBUF;

        // ---- bf16-A writeback (layer-0 only): smem fp32 -> row-major bf16 gmem ----
        if (WB) {
            if (MROWS == 64) {
                int row = tid >> 2, c0 = (tid & 3) * 8;
                const float* p = (const float*)(As + row * AST + c0 * 4);
                float4 v0 = *(const float4*)(p);
                float4 v1 = *(const float4*)(p + 4);
                uint4 o;
                o.x = pack_bf16x2(make_float2(v0.x, v0.y));
                o.y = pack_bf16x2(make_float2(v0.z, v0.w));
                o.z = pack_bf16x2(make_float2(v1.x, v1.y));
                o.w = pack_bf16x2(make_float2(v1.z, v1.w));
                *(uint4*)(Awb + (size_t)(m0 + row) * N_NODES + kt * KC + c0) = o;
            } else {
                int row = tid >> 3, c0 = (tid & 7) * 4;
                const float* p = (const float*)(As + row * AST + c0 * 4);
                float4 v0 = *(const float4*)(p);
                uint2 o;
                o.x = pack_bf16x2(make_float2(v0.x, v0.y));
                o.y = pack_bf16x2(make_float2(v0.z, v0.w));
                *(uint2*)(Awb + (size_t)(m0 + row) * N_NODES + kt * KC + c0) = o;
            }
        }

        #pragma unroll
        for (int ks = 0; ks < 2; ++ks) {
            uint32_t af[NMT][4], bf[2 * NP][2];
            #pragma unroll
            for (int mt = 0; mt < NMT; ++mt) {
                if (ABF) {
                    ldsm_x4(af[mt], Au + aoffL[mt][ks]);
                } else {
                    const char* p = As + afrag_base + mt * 16 * AST + ks * 64;
                    af[mt][0] = pack_bf16x2(*(const float2*)(p));
                    af[mt][1] = pack_bf16x2(*(const float2*)(p + 8 * AST));
                    af[mt][2] = pack_bf16x2(*(const float2*)(p + 32));
                    af[mt][3] = pack_bf16x2(*(const float2*)(p + 8 * AST + 32));
                }
            }
            #pragma unroll
            for (int np = 0; np < NP; ++np) {
                uint32_t tt[4];
                ldsm_x4(tt, Bb + boffL[np][ks]);
                bf[np * 2][0] = tt[0]; bf[np * 2][1] = tt[1];
                bf[np * 2 + 1][0] = tt[2]; bf[np * 2 + 1][1] = tt[3];
            }
            #pragma unroll
            for (int mt = 0; mt < NMT; ++mt)
                #pragma unroll
                for (int nt = 0; nt < 2 * NP; ++nt)
                    mma_bf16(acc[mt][nt], af[mt], bf[nt][0], bf[nt][1]);
        }

        st  = (st  == STAGES - 1) ? 0 : st + 1;
        sti = (sti == STAGES - 1) ? 0 : sti + 1;
    }

    // ---- epilogue ----
    const int tig = lane & 3;
    #pragma unroll
    for (int mt = 0; mt < NMT; ++mt) {
        int row = m0 + wm * WROWS + mt * 16 + g;
        #pragma unroll
        for (int nt = 0; nt < 2 * NP; ++nt) {
            int col = wn * NWID + nt * 8 + tig * 2;
            float* Cg = C0;
            int cc = col;
            if (NT == 2 && col >= 64) { Cg = C1; cc = col - 64; }
            *(float2*)(Cg + (size_t)row * 64 + cc)       = make_float2(acc[mt][nt][0], acc[mt][nt][1]);
            *(float2*)(Cg + (size_t)(row + 8) * 64 + cc) = make_float2(acc[mt][nt][2], acc[mt][nt][3]);
        }
    }
}

// Layer 0: fp32 A + bf16 writeback. Grid 384 single wave; pattern {NT1(M64), NT2(M32), NT2(M32)}.
__global__ void __launch_bounds__(256, 3)
gnn_gemm0_kernel(const float* __restrict__ Acl, const float* __restrict__ Aue) {
    extern __shared__ __align__(128) char smem[];
    const int b = blockIdx.x;
    const int q = b / 3, r = b - q * 3;
    if (r == 0) {
        gemm_body<1, 64, false, true, 4>(Acl, g_HclT, nullptr, g_Xc1, nullptr, g_AclB, q * 64, smem);
    } else {
        const int tile = q * 2 + r - 1;
        gemm_body<2, 32, false, true, 4>(Aue, g_HueT, g_HclT, g_Xc2, g_Xue, g_AueB, tile * 32, smem);
    }
}

// Layers 1-2: bf16 A (cached), ldmatrix A fragments. Deeper pipeline: NT1 6 stages, NT2 5 stages.
__global__ void __launch_bounds__(256, 3)
gnn_gemmb_kernel() {
    extern __shared__ __align__(128) char smem[];
    const int b = blockIdx.x;
    const int q = b / 3, r = b - q * 3;
    if (r == 0) {
        gemm_body<1, 64, true, false, 6>(g_AclB, g_HclT, nullptr, g_Xc1, nullptr, nullptr, q * 64, smem);
    } else {
        const int tile = q * 2 + r - 1;
        gemm_body<2, 32, true, false, 5>(g_AueB, g_HueT, g_HclT, g_Xc2, g_Xue, nullptr, tile * 32, smem);
    }
}

// ---------------- layer 0 H (in_dim = 2), writes H^T bf16 ----------------
__global__ void h0_kernel(const float* __restrict__ X1, const float* __restrict__ X2,
                          const float* __restrict__ XU,
                          const float* __restrict__ w1, const float* __restrict__ b1,
                          const float* __restrict__ w2, const float* __restrict__ b2,
                          const float* __restrict__ w3, const float* __restrict__ b3) {
    const int r = blockIdx.x * 256 + threadIdx.x;
    const float2 x1 = *(const float2*)(X1 + r * 2);
    const float2 x2 = *(const float2*)(X2 + r * 2);
    const float2 xu = *(const float2*)(XU + r * 2);
    #pragma unroll 8
    for (int c = 0; c < 64; ++c) {
        float h1 = relu_(fmaf(x1.x, __ldg(w1 + c), fmaf(x1.y, __ldg(w1 + 64 + c), __ldg(b1 + c))));
        float h2 = relu_(fmaf(x2.x, __ldg(w2 + c), fmaf(x2.y, __ldg(w2 + 64 + c), __ldg(b2 + c))));
        float h3 = relu_(fmaf(xu.x, __ldg(w3 + c), fmaf(xu.y, __ldg(w3 + 64 + c), __ldg(b3 + c))));
        g_HclT[c * N_NODES + r] = __float2bfloat16(h1 + h2);
        g_HueT[c * N_NODES + r] = __float2bfloat16(h3);
    }
}

// ---------------- layers 1..2 H (in_dim = 64), writes H^T bf16 ----------------
__global__ void __launch_bounds__(256) h_layer_kernel(const float* __restrict__ w1,
                                                      const float* __restrict__ b1,
                                                      const float* __restrict__ w2,
                                                      const float* __restrict__ b2,
                                                      const float* __restrict__ w3,
                                                      const float* __restrict__ b3) {
    __shared__ float xs1[16][64], xs2[16][64], xs3[16][64];
    __shared__ __align__(16) __nv_bfloat16 hs_cl[64][16];
    __shared__ __align__(16) __nv_bfloat16 hs_ue[64][16];
    const int tid = threadIdx.x;
    const int r0  = blockIdx.x * 16;
    #pragma unroll
    for (int i = 0; i < 4; ++i) {
        int idx = tid + i * 256;
        int r = idx >> 6, k = idx & 63;
        xs1[r][k] = g_Xc1[(size_t)(r0 + r) * 64 + k];
        xs2[r][k] = g_Xc2[(size_t)(r0 + r) * 64 + k];
        xs3[r][k] = g_Xue[(size_t)(r0 + r) * 64 + k];
    }
    __syncthreads();
    const int c  = tid & 63;
    const int rg = tid >> 6;
    float a1[4] = {0, 0, 0, 0}, a2[4] = {0, 0, 0, 0}, a3[4] = {0, 0, 0, 0};
    #pragma unroll 8
    for (int k = 0; k < 64; ++k) {
        float w1k = w1[k * 64 + c], w2k = w2[k * 64 + c], w3k = w3[k * 64 + c];
        #pragma unroll
        for (int i = 0; i < 4; ++i) {
            int r = rg + i * 4;
            a1[i] = fmaf(xs1[r][k], w1k, a1[i]);
            a2[i] = fmaf(xs2[r][k], w2k, a2[i]);
            a3[i] = fmaf(xs3[r][k], w3k, a3[i]);
        }
    }
    const float bb1 = b1[c], bb2 = b2[c], bb3 = b3[c];
    #pragma unroll
    for (int i = 0; i < 4; ++i) {
        int r = rg + i * 4;
        hs_cl[c][r] = __float2bfloat16(relu_(a1[i] + bb1) + relu_(a2[i] + bb2));
        hs_ue[c][r] = __float2bfloat16(relu_(a3[i] + bb3));
    }
    __syncthreads();
    if (tid < 128) {
        int cc = tid >> 1, hf = tid & 1;
        *(uint4*)(g_HclT + cc * N_NODES + r0 + hf * 8) = *(const uint4*)(&hs_cl[cc][hf * 8]);
    } else {
        int tt = tid - 128;
        int cc = tt >> 1, hf = tt & 1;
        *(uint4*)(g_HueT + cc * N_NODES + r0 + hf * 8) = *(const uint4*)(&hs_ue[cc][hf * 8]);
    }
}

// ---------------- layer 3: H_cl + column-sum partials (X updates are dead) ----------------
__global__ void __launch_bounds__(256) h_pool_kernel(const float* __restrict__ w1,
                                                     const float* __restrict__ b1,
                                                     const float* __restrict__ w2,
                                                     const float* __restrict__ b2) {
    __shared__ float xs1[16][64], xs2[16][64];
    __shared__ float red[4][64];
    const int tid = threadIdx.x;
    const int r0  = blockIdx.x * 16;
    #pragma unroll
    for (int i = 0; i < 4; ++i) {
        int idx = tid + i * 256;
        int r = idx >> 6, k = idx & 63;
        xs1[r][k] = g_Xc1[(size_t)(r0 + r) * 64 + k];
        xs2[r][k] = g_Xc2[(size_t)(r0 + r) * 64 + k];
    }
    __syncthreads();
    const int c  = tid & 63;
    const int rg = tid >> 6;
    float a1[4] = {0, 0, 0, 0}, a2[4] = {0, 0, 0, 0};
    #pragma unroll 8
    for (int k = 0; k < 64; ++k) {
        float w1k = w1[k * 64 + c], w2k = w2[k * 64 + c];
        #pragma unroll
        for (int i = 0; i < 4; ++i) {
            int r = rg + i * 4;
            a1[i] = fmaf(xs1[r][k], w1k, a1[i]);
            a2[i] = fmaf(xs2[r][k], w2k, a2[i]);
        }
    }
    const float bb1 = b1[c], bb2 = b2[c];
    float s = 0.0f;
    #pragma unroll
    for (int i = 0; i < 4; ++i) s += relu_(a1[i] + bb1) + relu_(a2[i] + bb2);
    red[rg][c] = s;
    __syncthreads();
    if (tid < 64)
        g_part[blockIdx.x * 64 + tid] = red[0][tid] + red[1][tid] + red[2][tid] + red[3][tid];
}

// ---------------- final: reduce partials + 2-layer MLP -> out[0] ----------------
__global__ void final_kernel(const float* __restrict__ Qw1, const float* __restrict__ Qb1,
                             const float* __restrict__ Qw2, const float* __restrict__ Qb2,
                             float* __restrict__ out) {
    __shared__ float red[4][64];
    __shared__ float pooled[64];
    __shared__ float z[64];
    int tid = threadIdx.x;
    int c = tid & 63, g = tid >> 6;
    float s = 0.0f;
    for (int p = g; p < 512; p += 4) s += g_part[p * 64 + c];
    red[g][c] = s;
    __syncthreads();
    if (tid < 64) pooled[tid] = red[0][tid] + red[1][tid] + red[2][tid] + red[3][tid];
    __syncthreads();
    if (tid < 64) {
        float a = Qb1[tid];
        #pragma unroll 8
        for (int i = 0; i < 64; ++i) a = fmaf(pooled[i], Qw1[i * 64 + tid], a);
        z[tid] = relu_(a);
    }
    __syncthreads();
    if (tid == 0) {
        float s2 = Qb2[0];
        for (int j = 0; j < 64; ++j) s2 = fmaf(z[j], Qw2[j], s2);
        out[0] = s2;
    }
}

// ---------------- launch ----------------
extern "C" void kernel_launch(void* const* d_in, const int* in_sizes, int n_in,
                              void* d_out, int out_size) {
    (void)in_sizes; (void)n_in; (void)out_size;
    const float* X1   = (const float*)d_in[0];
    const float* X2   = (const float*)d_in[1];
    const float* XU   = (const float*)d_in[2];
    const float* Acl  = (const float*)d_in[3];
    const float* Aue  = (const float*)d_in[4];
    const float* W1w0 = (const float*)d_in[5];
    const float* W1b0 = (const float*)d_in[6];
    const float* W1w  = (const float*)d_in[7];
    const float* W1b  = (const float*)d_in[8];
    const float* W2w0 = (const float*)d_in[9];
    const float* W2b0 = (const float*)d_in[10];
    const float* W2w  = (const float*)d_in[11];
    const float* W2b  = (const float*)d_in[12];
    const float* W3w0 = (const float*)d_in[13];
    const float* W3b0 = (const float*)d_in[14];
    const float* W3w  = (const float*)d_in[15];
    const float* W3b  = (const float*)d_in[16];
    const float* Qw1  = (const float*)d_in[17];
    const float* Qb1  = (const float*)d_in[18];
    const float* Qw2  = (const float*)d_in[19];
    const float* Qb2  = (const float*)d_in[20];
    float* out = (float*)d_out;

    const int DSMEM0 = 61440;  // fp32-A: 4*(5120+10240)
    const int DSMEMB = 64000;  // bf16-A: max(6*10240, 5*12800)
    cudaFuncSetAttribute(gnn_gemm0_kernel, cudaFuncAttributeMaxDynamicSharedMemorySize, DSMEM0);
    cudaFuncSetAttribute(gnn_gemmb_kernel, cudaFuncAttributeMaxDynamicSharedMemorySize, DSMEMB);

    // layer 0: fp32 A + bf16-A writeback
    h0_kernel<<<32, 256>>>(X1, X2, XU, W1w0, W1b0, W2w0, W2b0, W3w0, W3b0);
    gnn_gemm0_kernel<<<384, 256, DSMEM0>>>(Acl, Aue);

    // layers 1..2: bf16 A (cached), deeper pipeline
    for (int l = 1; l <= 2; ++l) {
        h_layer_kernel<<<512, 256>>>(W1w + (l - 1) * 4096, W1b + (l - 1) * 64,
                                     W2w + (l - 1) * 4096, W2b + (l - 1) * 64,
                                     W3w + (l - 1) * 4096, W3b + (l - 1) * 64);
        gnn_gemmb_kernel<<<384, 256, DSMEMB>>>();
    }

    // layer 3: H_cl only + pooling partials, then final MLP
    h_pool_kernel<<<512, 256>>>(W1w + 2 * 4096, W1b + 2 * 64, W2w + 2 * 4096, W2b + 2 * 64);
    final_kernel<<<1, 256>>>(Qw1, Qb1, Qw2, Qb2, out);
}

// round 17
// speedup vs baseline: 1.1710x; 1.1710x over previous
#include <cuda_runtime.h>
#include <cuda_bf16.h>
#include <cstdint>
#include <cstddef>

#define N_NODES 8192
#define DHID 64

// ---------------- scratch (device globals; no allocation allowed) ----------------
__device__ __align__(16) __nv_bfloat16 g_HclT[DHID * N_NODES];  // H_cl^T bf16 [64][8192]
__device__ __align__(16) __nv_bfloat16 g_HueT[DHID * N_NODES];  // H_ue^T bf16 [64][8192]
__device__ __align__(16) float g_Xc1[N_NODES * DHID];
__device__ __align__(16) float g_Xc2[N_NODES * DHID];
__device__ __align__(16) float g_Xue[N_NODES * DHID];
__device__ __align__(16) float g_part[512 * DHID];

__device__ __forceinline__ float relu_(float x) { return fmaxf(x, 0.0f); }

__device__ __forceinline__ uint32_t smem_u32(const void* p) {
    uint32_t a;
    asm("{ .reg .u64 t; cvta.to.shared.u64 t, %1; cvt.u32.u64 %0, t; }" : "=r"(a) : "l"(p));
    return a;
}

__device__ __forceinline__ void ldsm_x4(uint32_t* r, uint32_t addr) {
    asm volatile("ldmatrix.sync.aligned.m8n8.x4.shared.b16 {%0,%1,%2,%3}, [%4];"
                 : "=r"(r[0]), "=r"(r[1]), "=r"(r[2]), "=r"(r[3]) : "r"(addr));
}

__device__ __forceinline__ void mma_bf16(float* c, const uint32_t* a, uint32_t b0, uint32_t b1) {
    asm volatile(
        "mma.sync.aligned.m16n8k16.row.col.f32.bf16.bf16.f32 "
        "{%0,%1,%2,%3}, {%4,%5,%6,%7}, {%8,%9}, {%0,%1,%2,%3};"
        : "+f"(c[0]), "+f"(c[1]), "+f"(c[2]), "+f"(c[3])
        : "r"(a[0]), "r"(a[1]), "r"(a[2]), "r"(a[3]), "r"(b0), "r"(b1));
}

__device__ __forceinline__ uint32_t pack_bf16x2(float2 v) {
    __nv_bfloat162 b = __float22bfloat162_rn(v);
    return *(uint32_t*)&b;
}

#define CP_ASYNC16(smem, gptr) \
    asm volatile("cp.async.cg.shared.global [%0], [%1], 16;" :: "r"(smem), "l"(gptr))
#define CP_COMMIT() asm volatile("cp.async.commit_group;")
#define CP_WAIT2()  asm volatile("cp.async.wait_group 2;")

// ---------------- GEMM body (128 threads, 32x32 warp tiles) ----------------
// C[MROWS, ND] = A(fp32) @ Ht^T (Ht bf16 [n][k])
// NT=1: MROWS=64, ND=64,  warps 2M x 2N. C0 = g_Xc1 (Bt0 = HclT)
// NT=2: MROWS=32, ND=128, warps 1M x 4N. cols 0-63 -> C0=g_Xc2 (Bt0=HueT),
//                                        cols 64-127 -> C1=g_Xue (Bt1=HclT)
// Both: warp tile 32x32, per-stage smem 15360 B.
template <int NT, int MROWS>
__device__ __forceinline__ void gemm_body(const float* __restrict__ A,
                                          const __nv_bfloat16* __restrict__ Bt0,
                                          const __nv_bfloat16* __restrict__ Bt1,
                                          float* __restrict__ C0, float* __restrict__ C1,
                                          int m0, char* smem) {
    constexpr int ND     = 64 * NT;
    constexpr int KC     = 32;                 // k per chunk
    constexpr int NCH    = N_NODES / KC;       // 256 chunks
    constexpr int STAGES = 4;
    constexpr int ASTR   = 160;                // fp32 A row stride (128B data + 32 pad)
    constexpr int ABUF   = MROWS * ASTR;       // A bytes per stage (10240 / 5120)
    constexpr int BSTR   = 80;                 // bf16 B row stride
    constexpr int BBUF   = ND * BSTR;          // B bytes per stage (5120 / 10240)
    constexpr int NW     = (NT == 1) ? 2 : 4;  // N-warps
    constexpr int APT    = MROWS * 8 / 128;    // A cp.async slots per thread (4 / 2)
    constexpr int BPT    = ND * 4 / 128;       // B cp.async slots per thread (2 / 4)

    const int tid  = threadIdx.x;
    const int lane = tid & 31;
    const int wid  = tid >> 5;                 // 0..3
    const int wn   = wid & (NW - 1);           // N-warp index
    const int wm   = wid / NW;                 // M-warp index (0..MROWS/32-1)
    const int g    = lane >> 2;
    const int t    = lane & 3;

    const uint32_t sbu = smem_u32(smem);
    const uint32_t sA0 = sbu;                  // STAGES stages of A
    const uint32_t sB0 = sbu + STAGES * ABUF;  // STAGES stages of B

    // ---- A cp.async slot map: MROWS rows x 8 x 16B slots, APT per thread ----
    const float* gAp[APT];
    uint32_t aoffS[APT];
    #pragma unroll
    for (int i = 0; i < APT; ++i) {
        int slot = tid + i * 128;
        int row = slot >> 3, seg = slot & 7;
        gAp[i]   = A + (size_t)(m0 + row) * N_NODES + seg * 4;
        aoffS[i] = (uint32_t)(row * ASTR + seg * 16);
    }
    // ---- B cp.async slot map: ND rows x 4 x 16B slots, BPT per thread ----
    const __nv_bfloat16* gBp[BPT];
    uint32_t boffS[BPT];
    #pragma unroll
    for (int j = 0; j < BPT; ++j) {
        int slot = tid + j * 128;
        int row = slot >> 2, seg = slot & 3;
        const __nv_bfloat16* base = (NT == 2 && row >= 64)
            ? (Bt1 + (size_t)(row - 64) * N_NODES) : (Bt0 + (size_t)row * N_NODES);
        gBp[j]   = base + seg * 8;
        boffS[j] = (uint32_t)(row * BSTR + seg * 16);
    }

    auto ISSUE = [&](int kt) {
        const int s = kt & (STAGES - 1);
        const uint32_t sa = sA0 + s * ABUF;
        #pragma unroll
        for (int i = 0; i < APT; ++i)
            CP_ASYNC16(sa + aoffS[i], gAp[i] + (size_t)kt * KC);
        const uint32_t sb = sB0 + s * BBUF;
        #pragma unroll
        for (int j = 0; j < BPT; ++j)
            CP_ASYNC16(sb + boffS[j], gBp[j] + (size_t)kt * KC);
    };

    // ---- B ldmatrix lane offsets (validated layout, 80B stride); warp covers 32 cols ----
    uint32_t boffL[2][2];
    #pragma unroll
    for (int np = 0; np < 2; ++np)
        #pragma unroll
        for (int ks = 0; ks < 2; ++ks)
            boffL[np][ks] = (uint32_t)((wn * 32 + np * 16 + (lane >> 4) * 8 + (lane & 7)) * BSTR +
                                       (ks * 16 + ((lane >> 3) & 1) * 8) * 2);

    // ---- A fragment base (fp32 smem, LDS.64 + cvt path); warp covers 32 rows ----
    const int afrag_base = (wm * 32 + g) * ASTR + t * 8;

    float acc[2][4][4];   // [m-subtile][n-tile][4]
    #pragma unroll
    for (int mt = 0; mt < 2; ++mt)
        #pragma unroll
        for (int nt = 0; nt < 4; ++nt)
            #pragma unroll
            for (int i = 0; i < 4; ++i) acc[mt][nt][i] = 0.0f;

    // ---- prologue: fill STAGES-1 stages ----
    #pragma unroll
    for (int s = 0; s < STAGES - 1; ++s) { ISSUE(s); CP_COMMIT(); }

    for (int kt = 0; kt < NCH; ++kt) {
        const int st = kt & (STAGES - 1);
        CP_WAIT2();
        __syncthreads();

        if (kt + STAGES - 1 < NCH) ISSUE(kt + STAGES - 1);
        CP_COMMIT();

        const char*    Ab = smem + st * ABUF + afrag_base;
        const uint32_t Bb = sB0 + st * BBUF;

        #pragma unroll
        for (int ks = 0; ks < 2; ++ks) {
            uint32_t af[2][4], bf[4][2];
            #pragma unroll
            for (int mt = 0; mt < 2; ++mt) {
                const char* p = Ab + mt * 16 * ASTR + ks * 64;
                af[mt][0] = pack_bf16x2(*(const float2*)(p));
                af[mt][1] = pack_bf16x2(*(const float2*)(p + 8 * ASTR));
                af[mt][2] = pack_bf16x2(*(const float2*)(p + 32));
                af[mt][3] = pack_bf16x2(*(const float2*)(p + 8 * ASTR + 32));
            }
            #pragma unroll
            for (int np = 0; np < 2; ++np) {
                uint32_t tt[4];
                ldsm_x4(tt, Bb + boffL[np][ks]);
                bf[np * 2][0] = tt[0]; bf[np * 2][1] = tt[1];
                bf[np * 2 + 1][0] = tt[2]; bf[np * 2 + 1][1] = tt[3];
            }
            #pragma unroll
            for (int mt = 0; mt < 2; ++mt)
                #pragma unroll
                for (int nt = 0; nt < 4; ++nt)
                    mma_bf16(acc[mt][nt], af[mt], bf[nt][0], bf[nt][1]);
        }
    }

    // ---- epilogue ----
    const int tig = lane & 3;
    #pragma unroll
    for (int mt = 0; mt < 2; ++mt) {
        int row = m0 + wm * 32 + mt * 16 + g;
        #pragma unroll
        for (int nt = 0; nt < 4; ++nt) {
            int col = wn * 32 + nt * 8 + tig * 2;
            float* Cg = C0;
            int cc = col;
            if (NT == 2 && col >= 64) { Cg = C1; cc = col - 64; }
            *(float2*)(Cg + (size_t)row * 64 + cc)       = make_float2(acc[mt][nt][0], acc[mt][nt][1]);
            *(float2*)(Cg + (size_t)(row + 8) * 64 + cc) = make_float2(acc[mt][nt][2], acc[mt][nt][3]);
        }
    }
}

// Grid 384, 128 threads. Pattern per 3 blocks: {NT1(M64), NT2(M32), NT2(M32)}.
__global__ void __launch_bounds__(128, 3)
gnn_gemm_kernel(const float* __restrict__ Acl, const float* __restrict__ Aue) {
    extern __shared__ __align__(128) char smem[];   // 4 * 15360 = 61440 B both variants
    const int b = blockIdx.x;
    const int q = b / 3, r = b - q * 3;
    if (r == 0) {
        gemm_body<1, 64>(Acl, g_HclT, nullptr, g_Xc1, nullptr, q * 64, smem);
    } else {
        const int tile = q * 2 + r - 1;             // 0..255
        gemm_body<2, 32>(Aue, g_HueT, g_HclT, g_Xc2, g_Xue, tile * 32, smem);
    }
}

// ---------------- layer 0 H (in_dim = 2), writes H^T bf16 ----------------
__global__ void h0_kernel(const float* __restrict__ X1, const float* __restrict__ X2,
                          const float* __restrict__ XU,
                          const float* __restrict__ w1, const float* __restrict__ b1,
                          const float* __restrict__ w2, const float* __restrict__ b2,
                          const float* __restrict__ w3, const float* __restrict__ b3) {
    const int r = blockIdx.x * 256 + threadIdx.x;
    const float2 x1 = *(const float2*)(X1 + r * 2);
    const float2 x2 = *(const float2*)(X2 + r * 2);
    const float2 xu = *(const float2*)(XU + r * 2);
    #pragma unroll 8
    for (int c = 0; c < 64; ++c) {
        float h1 = relu_(fmaf(x1.x, __ldg(w1 + c), fmaf(x1.y, __ldg(w1 + 64 + c), __ldg(b1 + c))));
        float h2 = relu_(fmaf(x2.x, __ldg(w2 + c), fmaf(x2.y, __ldg(w2 + 64 + c), __ldg(b2 + c))));
        float h3 = relu_(fmaf(xu.x, __ldg(w3 + c), fmaf(xu.y, __ldg(w3 + 64 + c), __ldg(b3 + c))));
        g_HclT[c * N_NODES + r] = __float2bfloat16(h1 + h2);
        g_HueT[c * N_NODES + r] = __float2bfloat16(h3);
    }
}

// ---------------- layers 1..2 H (in_dim = 64), writes H^T bf16 ----------------
__global__ void __launch_bounds__(256) h_layer_kernel(const float* __restrict__ w1,
                                                      const float* __restrict__ b1,
                                                      const float* __restrict__ w2,
                                                      const float* __restrict__ b2,
                                                      const float* __restrict__ w3,
                                                      const float* __restrict__ b3) {
    __shared__ float xs1[16][64], xs2[16][64], xs3[16][64];
    __shared__ __align__(16) __nv_bfloat16 hs_cl[64][16];
    __shared__ __align__(16) __nv_bfloat16 hs_ue[64][16];
    const int tid = threadIdx.x;
    const int r0  = blockIdx.x * 16;
    #pragma unroll
    for (int i = 0; i < 4; ++i) {
        int idx = tid + i * 256;
        int r = idx >> 6, k = idx & 63;
        xs1[r][k] = g_Xc1[(size_t)(r0 + r) * 64 + k];
        xs2[r][k] = g_Xc2[(size_t)(r0 + r) * 64 + k];
        xs3[r][k] = g_Xue[(size_t)(r0 + r) * 64 + k];
    }
    __syncthreads();
    const int c  = tid & 63;
    const int rg = tid >> 6;
    float a1[4] = {0, 0, 0, 0}, a2[4] = {0, 0, 0, 0}, a3[4] = {0, 0, 0, 0};
    #pragma unroll 8
    for (int k = 0; k < 64; ++k) {
        float w1k = w1[k * 64 + c], w2k = w2[k * 64 + c], w3k = w3[k * 64 + c];
        #pragma unroll
        for (int i = 0; i < 4; ++i) {
            int r = rg + i * 4;
            a1[i] = fmaf(xs1[r][k], w1k, a1[i]);
            a2[i] = fmaf(xs2[r][k], w2k, a2[i]);
            a3[i] = fmaf(xs3[r][k], w3k, a3[i]);
        }
    }
    const float bb1 = b1[c], bb2 = b2[c], bb3 = b3[c];
    #pragma unroll
    for (int i = 0; i < 4; ++i) {
        int r = rg + i * 4;
        hs_cl[c][r] = __float2bfloat16(relu_(a1[i] + bb1) + relu_(a2[i] + bb2));
        hs_ue[c][r] = __float2bfloat16(relu_(a3[i] + bb3));
    }
    __syncthreads();
    if (tid < 128) {
        int cc = tid >> 1, hf = tid & 1;
        *(uint4*)(g_HclT + cc * N_NODES + r0 + hf * 8) = *(const uint4*)(&hs_cl[cc][hf * 8]);
    } else {
        int tt = tid - 128;
        int cc = tt >> 1, hf = tt & 1;
        *(uint4*)(g_HueT + cc * N_NODES + r0 + hf * 8) = *(const uint4*)(&hs_ue[cc][hf * 8]);
    }
}

// ---------------- layer 3: H_cl + column-sum partials (X updates are dead) ----------------
__global__ void __launch_bounds__(256) h_pool_kernel(const float* __restrict__ w1,
                                                     const float* __restrict__ b1,
                                                     const float* __restrict__ w2,
                                                     const float* __restrict__ b2) {
    __shared__ float xs1[16][64], xs2[16][64];
    __shared__ float red[4][64];
    const int tid = threadIdx.x;
    const int r0  = blockIdx.x * 16;
    #pragma unroll
    for (int i = 0; i < 4; ++i) {
        int idx = tid + i * 256;
        int r = idx >> 6, k = idx & 63;
        xs1[r][k] = g_Xc1[(size_t)(r0 + r) * 64 + k];
        xs2[r][k] = g_Xc2[(size_t)(r0 + r) * 64 + k];
    }
    __syncthreads();
    const int c  = tid & 63;
    const int rg = tid >> 6;
    float a1[4] = {0, 0, 0, 0}, a2[4] = {0, 0, 0, 0};
    #pragma unroll 8
    for (int k = 0; k < 64; ++k) {
        float w1k = w1[k * 64 + c], w2k = w2[k * 64 + c];
        #pragma unroll
        for (int i = 0; i < 4; ++i) {
            int r = rg + i * 4;
            a1[i] = fmaf(xs1[r][k], w1k, a1[i]);
            a2[i] = fmaf(xs2[r][k], w2k, a2[i]);
        }
    }
    const float bb1 = b1[c], bb2 = b2[c];
    float s = 0.0f;
    #pragma unroll
    for (int i = 0; i < 4; ++i) s += relu_(a1[i] + bb1) + relu_(a2[i] + bb2);
    red[rg][c] = s;
    __syncthreads();
    if (tid < 64)
        g_part[blockIdx.x * 64 + tid] = red[0][tid] + red[1][tid] + red[2][tid] + red[3][tid];
}

// ---------------- final: reduce partials + 2-layer MLP -> out[0] ----------------
__global__ void final_kernel(const float* __restrict__ Qw1, const float* __restrict__ Qb1,
                             const float* __restrict__ Qw2, const float* __restrict__ Qb2,
                             float* __restrict__ out) {
    __shared__ float red[4][64];
    __shared__ float pooled[64];
    __shared__ float z[64];
    int tid = threadIdx.x;
    int c = tid & 63, g = tid >> 6;
    float s = 0.0f;
    for (int p = g; p < 512; p += 4) s += g_part[p * 64 + c];
    red[g][c] = s;
    __syncthreads();
    if (tid < 64) pooled[tid] = red[0][tid] + red[1][tid] + red[2][tid] + red[3][tid];
    __syncthreads();
    if (tid < 64) {
        float a = Qb1[tid];
        #pragma unroll 8
        for (int i = 0; i < 64; ++i) a = fmaf(pooled[i], Qw1[i * 64 + tid], a);
        z[tid] = relu_(a);
    }
    __syncthreads();
    if (tid == 0) {
        float s2 = Qb2[0];
        for (int j = 0; j < 64; ++j) s2 = fmaf(z[j], Qw2[j], s2);
        out[0] = s2;
    }
}

// ---------------- launch ----------------
extern "C" void kernel_launch(void* const* d_in, const int* in_sizes, int n_in,
                              void* d_out, int out_size) {
    (void)in_sizes; (void)n_in; (void)out_size;
    const float* X1   = (const float*)d_in[0];
    const float* X2   = (const float*)d_in[1];
    const float* XU   = (const float*)d_in[2];
    const float* Acl  = (const float*)d_in[3];
    const float* Aue  = (const float*)d_in[4];
    const float* W1w0 = (const float*)d_in[5];
    const float* W1b0 = (const float*)d_in[6];
    const float* W1w  = (const float*)d_in[7];
    const float* W1b  = (const float*)d_in[8];
    const float* W2w0 = (const float*)d_in[9];
    const float* W2b0 = (const float*)d_in[10];
    const float* W2w  = (const float*)d_in[11];
    const float* W2b  = (const float*)d_in[12];
    const float* W3w0 = (const float*)d_in[13];
    const float* W3b0 = (const float*)d_in[14];
    const float* W3w  = (const float*)d_in[15];
    const float* W3b  = (const float*)d_in[16];
    const float* Qw1  = (const float*)d_in[17];
    const float* Qb1  = (const float*)d_in[18];
    const float* Qw2  = (const float*)d_in[19];
    const float* Qb2  = (const float*)d_in[20];
    float* out = (float*)d_out;

    const int DSMEM = 61440;  // 4 * 15360, both variants -> 3 CTAs/SM, grid 384 single wave
    cudaFuncSetAttribute(gnn_gemm_kernel, cudaFuncAttributeMaxDynamicSharedMemorySize, DSMEM);

    // layer 0
    h0_kernel<<<32, 256>>>(X1, X2, XU, W1w0, W1b0, W2w0, W2b0, W3w0, W3b0);
    gnn_gemm_kernel<<<384, 128, DSMEM>>>(Acl, Aue);

    // layers 1..2
    for (int l = 1; l <= 2; ++l) {
        h_layer_kernel<<<512, 256>>>(W1w + (l - 1) * 4096, W1b + (l - 1) * 64,
                                     W2w + (l - 1) * 4096, W2b + (l - 1) * 64,
                                     W3w + (l - 1) * 4096, W3b + (l - 1) * 64);
        gnn_gemm_kernel<<<384, 128, DSMEM>>>(Acl, Aue);
    }

    // layer 3: H_cl only + pooling partials, then final MLP
    h_pool_kernel<<<512, 256>>>(W1w + 2 * 4096, W1b + 2 * 64, W2w + 2 * 4096, W2b + 2 * 64);
    final_kernel<<<1, 256>>>(Qw1, Qb1, Qw2, Qb2, out);
}